// round 7
// baseline (speedup 1.0000x reference)
#include <cuda_runtime.h>
#include <cuda_fp16.h>
#include <math.h>
#include <stdint.h>

#define NN 512
#define TT 12
#define NJ 24576
#define NNNN (NN*NN)

// ---------------- device scratch ----------------
__device__ float g_smW1[40*20];
__device__ float g_smW2[40*20];
__device__ float g_e1[NN*20];
__device__ float g_e2[NN*20];
__device__ float g_A[NN*NN];
__device__ float g_d[NN];
__device__ float g_P[(size_t)9*NNNN];            // powers Ls^1..Ls^9 (slot k-1), slot 7 unused
__device__ __align__(16) __half g_Zh[(size_t)10*NNNN]; // pieces fp16, [p][v][w]
__device__ __align__(16) __half g_xh[(size_t)NN*NJ];   // [v][(b*12+t)*64+c]
__device__ __align__(16) __half g_Wh[10*64*64];        // [p][c][o]

// power-product table: P_C = P_A @ P_B (slot indices)
__device__ const int POW_A[7] = {0,0,1,1,2,2,3};
__device__ const int POW_B[7] = {0,1,1,2,2,3,4};
__device__ const int POW_C[7] = {1,2,3,4,5,6,8};

// ---------------- helpers ----------------
__device__ __forceinline__ unsigned f2tf(float f) {
    unsigned u;
    asm("cvt.rna.tf32.f32 %0, %1;" : "=r"(u) : "f"(f));
    return u;
}
__device__ __forceinline__ void mma_tf32(float c[4], const unsigned a[4], const unsigned b[2]) {
    asm volatile("mma.sync.aligned.m16n8k8.row.col.f32.tf32.tf32.f32 "
        "{%0,%1,%2,%3}, {%4,%5,%6,%7}, {%8,%9}, {%0,%1,%2,%3};"
        : "+f"(c[0]), "+f"(c[1]), "+f"(c[2]), "+f"(c[3])
        : "r"(a[0]), "r"(a[1]), "r"(a[2]), "r"(a[3]), "r"(b[0]), "r"(b[1]));
}
__device__ __forceinline__ void mma_f16(float c[4], const unsigned a[4], const unsigned b[2]) {
    asm volatile("mma.sync.aligned.m16n8k16.row.col.f32.f16.f16.f32 "
        "{%0,%1,%2,%3}, {%4,%5,%6,%7}, {%8,%9}, {%0,%1,%2,%3};"
        : "+f"(c[0]), "+f"(c[1]), "+f"(c[2]), "+f"(c[3])
        : "r"(a[0]), "r"(a[1]), "r"(a[2]), "r"(a[3]), "r"(b[0]), "r"(b[1]));
}
__device__ __forceinline__ void ldm4t(unsigned r[4], const __half* p) {
    unsigned a = (unsigned)__cvta_generic_to_shared((void*)p);
    asm volatile("ldmatrix.sync.aligned.m8n8.x4.trans.shared.b16 {%0,%1,%2,%3}, [%4];"
        : "=r"(r[0]), "=r"(r[1]), "=r"(r[2]), "=r"(r[3]) : "r"(a));
}
__device__ __forceinline__ void ldm4(unsigned r[4], const __half* p) {
    unsigned a = (unsigned)__cvta_generic_to_shared((void*)p);
    asm volatile("ldmatrix.sync.aligned.m8n8.x4.shared.b16 {%0,%1,%2,%3}, [%4];"
        : "=r"(r[0]), "=r"(r[1]), "=r"(r[2]), "=r"(r[3]) : "r"(a));
}
__device__ __forceinline__ void cp16(const __half* smem_dst, const __half* gsrc) {
    unsigned sa = (unsigned)__cvta_generic_to_shared((void*)smem_dst);
    asm volatile("cp.async.ca.shared.global [%0], [%1], 16;" :: "r"(sa), "l"(gsrc));
}
__device__ __forceinline__ void cp_commit() { asm volatile("cp.async.commit_group;"); }

// ---------------- preprocessing ----------------
__global__ void k_softmax(const float* __restrict__ W1, const float* __restrict__ W2) {
    int t = threadIdx.x;
    if (t >= 40) return;
    const float* W = (t < 20) ? W1 : W2;
    float* S = (t < 20) ? g_smW1 : g_smW2;
    int c = (t < 20) ? t : t - 20;
    float m = -1e30f;
    for (int r = 0; r < 40; r++) m = fmaxf(m, W[r*20 + c]);
    float e[40];
    float s = 0.f;
    for (int r = 0; r < 40; r++) { e[r] = expf(W[r*20 + c] - m); s += e[r]; }
    float inv = 1.f / s;
    for (int r = 0; r < 40; r++) S[r*20 + c] = e[r] * inv;
}

__global__ void k_embed(const float* __restrict__ emb) {
    int i = blockIdx.x;
    __shared__ float es[40];
    __shared__ float r1[20], r2[20], nrm[2];
    int tid = threadIdx.x;
    if (tid < 40) es[tid] = emb[i*40 + tid];
    __syncthreads();
    if (tid < 20) {
        float s = 0.f;
        for (int q = 0; q < 40; q++) s += es[q] * g_smW1[q*20 + tid];
        r1[tid] = s;
    } else if (tid < 40) {
        int c = tid - 20;
        float s = 0.f;
        for (int q = 0; q < 40; q++) s += es[q] * g_smW2[q*20 + c];
        r2[c] = s;
    }
    __syncthreads();
    if (tid < 2) {
        const float* rr = tid ? r2 : r1;
        float s = 0.f;
        for (int q = 0; q < 20; q++) s += rr[q]*rr[q];
        nrm[tid] = sqrtf(s) + 1e-8f;
    }
    __syncthreads();
    if (tid < 20)      g_e1[i*20 + tid]       = r1[tid]      / nrm[0];
    else if (tid < 40) g_e2[i*20 + (tid-20)]  = r2[tid-20]   / nrm[1];
}

__global__ void k_buildA(const float* __restrict__ adj) {
    int i = blockIdx.x;
    __shared__ float e1s[20];
    __shared__ float red[256];
    int tid = threadIdx.x;
    if (tid < 20) e1s[tid] = g_e1[i*20 + tid];
    __syncthreads();
    float rs = 0.f;
    for (int j = tid; j < NN; j += 256) {
        float dot = 0.f;
        #pragma unroll
        for (int q = 0; q < 20; q++) dot += e1s[q] * g_e2[j*20 + q];
        float ad = adj[i*NN + j];
        float a = (ad > 0.f) ? (dot + ad) : 9e-15f;
        g_A[i*NN + j] = a;
        rs += a;
    }
    red[tid] = rs; __syncthreads();
    for (int s = 128; s > 0; s >>= 1) {
        if (tid < s) red[tid] += red[tid + s];
        __syncthreads();
    }
    if (tid == 0) g_d[i] = 1.f / sqrtf(red[0]);
}

// P1 = Ls
__global__ void k_ls() {
    int i = blockIdx.x;
    float di = g_d[i];
    for (int j = threadIdx.x; j < NN; j += 256)
        g_P[(size_t)i*NN + j] = -(di * g_A[i*NN + j] * g_d[j]);
}

// batched 512^3 tf32 gemm: P_C[z] = P_A[z] @ P_B[z]
__global__ void __launch_bounds__(256) k_pow(int base) {
    int z = base + blockIdx.z;
    const float* A = g_P + (size_t)POW_A[z]*NNNN;
    const float* B = g_P + (size_t)POW_B[z]*NNNN;
    float*       C = g_P + (size_t)POW_C[z]*NNNN;

    __shared__ unsigned As[64*36];
    __shared__ unsigned Bs[32*68];
    const int tid = threadIdx.x;
    const int wid = tid >> 5, lane = tid & 31;
    const int qr = lane >> 2, qc = lane & 3;
    const int warpM = (wid >> 2) * 32;
    const int warpN = (wid & 3) * 16;
    const int row0 = blockIdx.y * 64, col0 = blockIdx.x * 64;
    float acc[2][2][4] = {};
    for (int k0 = 0; k0 < 512; k0 += 32) {
        #pragma unroll
        for (int l = 0; l < 2; l++) {
            int idx = tid + l*256;
            int m = idx >> 3, k4 = (idx & 7) << 2;
            float4 v = *(const float4*)(A + (size_t)(row0 + m)*512 + k0 + k4);
            unsigned* d = &As[m*36 + k4];
            d[0]=f2tf(v.x); d[1]=f2tf(v.y); d[2]=f2tf(v.z); d[3]=f2tf(v.w);
        }
        #pragma unroll
        for (int l = 0; l < 2; l++) {
            int idx = tid + l*256;
            int kr = idx >> 4, n4 = (idx & 15) << 2;
            float4 v = *(const float4*)(B + (size_t)(k0 + kr)*512 + col0 + n4);
            unsigned* d = &Bs[kr*68 + n4];
            d[0]=f2tf(v.x); d[1]=f2tf(v.y); d[2]=f2tf(v.z); d[3]=f2tf(v.w);
        }
        __syncthreads();
        #pragma unroll
        for (int kk = 0; kk < 4; kk++) {
            int kb = kk*8;
            unsigned a[2][4], b[2][2];
            #pragma unroll
            for (int mf = 0; mf < 2; mf++) {
                int m = warpM + mf*16 + qr;
                a[mf][0] = As[m*36 + kb + qc];
                a[mf][1] = As[(m+8)*36 + kb + qc];
                a[mf][2] = As[m*36 + kb + qc + 4];
                a[mf][3] = As[(m+8)*36 + kb + qc + 4];
            }
            #pragma unroll
            for (int nf = 0; nf < 2; nf++) {
                int n = warpN + nf*8 + qr;
                b[nf][0] = Bs[(kb+qc)*68 + n];
                b[nf][1] = Bs[(kb+qc+4)*68 + n];
            }
            #pragma unroll
            for (int mf = 0; mf < 2; mf++)
                #pragma unroll
                for (int nf = 0; nf < 2; nf++)
                    mma_tf32(acc[mf][nf], a[mf], b[nf]);
        }
        __syncthreads();
    }
    #pragma unroll
    for (int mf = 0; mf < 2; mf++)
        #pragma unroll
        for (int nf = 0; nf < 2; nf++)
            #pragma unroll
            for (int e = 0; e < 4; e++) {
                int i = row0 + warpM + mf*16 + qr + (e >> 1)*8;
                int j = col0 + warpN + nf*8 + qc*2 + (e & 1);
                C[(size_t)i*512 + j] = acc[mf][nf][e];
            }
}

// build all 10 fp16 pieces from powers (elementwise, coalesced)
__global__ void k_combine() {
    int idx = blockIdx.x*256 + threadIdx.x;   // 65536 float4 groups
    size_t off = (size_t)idx*4;
    int v = (int)(off >> 9), w0 = (int)(off & 511);
    float4 q1 = *(const float4*)(g_P + 0*(size_t)NNNN + off);
    float4 q2 = *(const float4*)(g_P + 1*(size_t)NNNN + off);
    float4 q3 = *(const float4*)(g_P + 2*(size_t)NNNN + off);
    float4 q4 = *(const float4*)(g_P + 3*(size_t)NNNN + off);
    float4 q5 = *(const float4*)(g_P + 4*(size_t)NNNN + off);
    float4 q6 = *(const float4*)(g_P + 5*(size_t)NNNN + off);
    float4 q7 = *(const float4*)(g_P + 6*(size_t)NNNN + off);
    float4 q9 = *(const float4*)(g_P + 8*(size_t)NNNN + off);
    float P1[4] = {q1.x,q1.y,q1.z,q1.w};
    float P2[4] = {q2.x,q2.y,q2.z,q2.w};
    float P3[4] = {q3.x,q3.y,q3.z,q3.w};
    float P4[4] = {q4.x,q4.y,q4.z,q4.w};
    float P5[4] = {q5.x,q5.y,q5.z,q5.w};
    float P6[4] = {q6.x,q6.y,q6.z,q6.w};
    float P7[4] = {q7.x,q7.y,q7.z,q7.w};
    float P9[4] = {q9.x,q9.y,q9.z,q9.w};
    float Z[10][4];
    #pragma unroll
    for (int i = 0; i < 4; i++) {
        float D = (w0 + i == v) ? 1.f : 0.f;
        Z[0][i] = P1[i];
        Z[1][i] = P2[i];
        Z[2][i] = P3[i];
        Z[3][i] = 2.f*P2[i] - D;                                     // T2
        Z[4][i] = 4.f*P4[i] - 4.f*P2[i] + D;                         // T2^2
        Z[5][i] = 8.f*P6[i] - 12.f*P4[i] + 6.f*P2[i] - D;            // T2^3
        Z[6][i] = 4.f*P3[i] - 3.f*P1[i];                             // T3
        Z[7][i] = 16.f*P6[i] - 24.f*P4[i] + 9.f*P2[i];               // T3^2
        Z[8][i] = 64.f*P9[i] - 144.f*P7[i] + 108.f*P5[i] - 27.f*P3[i]; // T3^3
        Z[9][i] = D;
    }
    #pragma unroll
    for (int p = 0; p < 10; p++) {
        __half2 h0 = __floats2half2_rn(Z[p][0], Z[p][1]);
        __half2 h1 = __floats2half2_rn(Z[p][2], Z[p][3]);
        uint2 u; u.x = *(unsigned*)&h0; u.y = *(unsigned*)&h1;
        *(uint2*)(g_Zh + (size_t)p*NNNN + off) = u;
    }
}

// g_xh[v][(b*12+t)*64+c] = x[b][v][t][c]
__global__ void k_xh(const float* __restrict__ x) {
    int b = blockIdx.x, v = blockIdx.y;
    int tc = threadIdx.x * 4;
    float4 f = *(const float4*)(x + ((size_t)(b*512 + v)*12)*64 + tc);
    __half2 h0 = __floats2half2_rn(f.x, f.y), h1 = __floats2half2_rn(f.z, f.w);
    uint2 u; u.x = *(unsigned*)&h0; u.y = *(unsigned*)&h1;
    *(uint2*)(g_xh + (size_t)v*NJ + b*768 + tc) = u;
}

__global__ void k_packWh(const float* __restrict__ mlp_w) {
    int idx = blockIdx.x*1024 + threadIdx.x;   // 40960 total
    int p = idx >> 12, rem = idx & 4095;
    int c = rem >> 6, o = rem & 63;
    float v;
    if (p < 9) v = mlp_w[o*832 + 256 + p*64 + c];
    else       v = mlp_w[o*832 + c] + mlp_w[o*832 + 64 + c]
                 + mlp_w[o*832 + 128 + c] + mlp_w[o*832 + 192 + c];
    g_Wh[idx] = __float2half(v);
}

// ---------------- fused main kernel: 4-stage ring, 1 barrier/chunk ----------------
#define STG 8704          // 64*136 halves per stage
__global__ void __launch_bounds__(512, 1) k_main(const float* __restrict__ x,
                                                 const float* __restrict__ bias,
                                                 float* __restrict__ out) {
    extern __shared__ __half sm[];
    __half* SA = sm;                     // 4 stages
    __half* SB = sm + 4*STG;             // 4 stages
    __half* Gs = sm + 8*STG;             // [128][136]
    __half* Wb = Gs + 128*136;           // 2 x [64][72]
    float*  Cs = (float*)sm;             // epilogue overlay (128x132 fp32)

    const int tid = threadIdx.x;
    const int wid = tid >> 5, lane = tid & 31;
    const int qr = lane >> 2, qc = lane & 3;
    const int warpM = (wid >> 2) * 32;        // 0,32,64,96
    const int warpN = (wid & 3) * 32;         // 0,32,64,96
    const int rowBase = blockIdx.y * 128;
    const int colBase = blockIdx.x * 128;

    const int g = lane >> 3, lrow = lane & 7;
    const int aTrow = (g >> 1)*8 + lrow, aTcol = (g & 1)*8;
    const int bTrow = (g & 1)*8 + lrow, bTcol = (g >> 1)*8;

    float acc[2][4][4] = {};
    float oacc[2][4][4] = {};

    const int wkr = tid >> 3, wseg = tid & 7;          // W-load task (512 tasks)

    // preload W0 + chunks 0..2 (3 groups)
    cp16(&Wb[wkr*72 + wseg*8], g_Wh + (size_t)wkr*64 + wseg*8);
    #pragma unroll
    for (int st = 0; st < 3; st++) {
        #pragma unroll
        for (int l = 0; l < 2; l++) {
            int idx = tid + l*512;
            int kr = idx >> 4, seg = idx & 15;
            cp16(&SA[st*STG + kr*136 + seg*8], g_Zh + (size_t)(st*64 + kr)*512 + rowBase + seg*8);
            cp16(&SB[st*STG + kr*136 + seg*8], g_xh + (size_t)(st*64 + kr)*NJ + colBase + seg*8);
        }
        cp_commit();
    }

    for (int s = 0; s < 72; s++) {
        int kc = s & 7;
        asm volatile("cp.async.wait_group 2;");
        __syncthreads();
        int s3 = s + 3;
        if (s3 < 72) {
            int p3 = s3 >> 3, kc3 = s3 & 7, st = s3 & 3;
            #pragma unroll
            for (int l = 0; l < 2; l++) {
                int idx = tid + l*512;
                int kr = idx >> 4, seg = idx & 15;
                cp16(&SA[st*STG + kr*136 + seg*8],
                     g_Zh + (size_t)(p3*512 + kc3*64 + kr)*512 + rowBase + seg*8);
                cp16(&SB[st*STG + kr*136 + seg*8],
                     g_xh + (size_t)(kc3*64 + kr)*NJ + colBase + seg*8);
            }
            if (kc3 == 0)
                cp16(&Wb[(p3 & 1)*4608 + wkr*72 + wseg*8],
                     g_Wh + (size_t)(p3*64 + wkr)*64 + wseg*8);
        } else if (s3 == 72) {
            cp16(&Wb[4608 + wkr*72 + wseg*8], g_Wh + (size_t)(9*64 + wkr)*64 + wseg*8);
        }
        cp_commit();

        const __half* A = SA + (s & 3)*STG;
        const __half* B = SB + (s & 3)*STG;
        #pragma unroll
        for (int kk = 0; kk < 4; kk++) {
            int kb = kk*16;
            unsigned a[2][4], b[4][2];
            #pragma unroll
            for (int mf = 0; mf < 2; mf++)
                ldm4t(a[mf], A + (kb + aTrow)*136 + warpM + mf*16 + aTcol);
            #pragma unroll
            for (int nfp = 0; nfp < 2; nfp++) {
                unsigned r[4];
                ldm4t(r, B + (kb + bTrow)*136 + warpN + nfp*16 + bTcol);
                b[2*nfp][0] = r[0]; b[2*nfp][1] = r[1];
                b[2*nfp+1][0] = r[2]; b[2*nfp+1][1] = r[3];
            }
            #pragma unroll
            for (int mf = 0; mf < 2; mf++)
                #pragma unroll
                for (int nf = 0; nf < 4; nf++)
                    mma_f16(acc[mf][nf], a[mf], b[nf]);
        }

        if (kc == 7) {
            int p = s >> 3;
            // acc -> Gs fp16, reset acc
            #pragma unroll
            for (int mf = 0; mf < 2; mf++)
                #pragma unroll
                for (int nf = 0; nf < 4; nf++) {
                    int r = warpM + mf*16 + qr, c = warpN + nf*8 + qc*2;
                    __half2 h0 = __floats2half2_rn(acc[mf][nf][0], acc[mf][nf][1]);
                    __half2 h1 = __floats2half2_rn(acc[mf][nf][2], acc[mf][nf][3]);
                    *(__half2*)&Gs[r*136 + c] = h0;
                    *(__half2*)&Gs[(r+8)*136 + c] = h1;
                    acc[mf][nf][0]=0.f; acc[mf][nf][1]=0.f; acc[mf][nf][2]=0.f; acc[mf][nf][3]=0.f;
                }
            __syncthreads();
            // GEMM2: oacc += Gs(bt-slice) @ W_p
            const int btoff = warpN & 64;
            const int obase = warpN & 32;
            const __half* Wp = Wb + (p & 1)*4608;
            #pragma unroll
            for (int kk = 0; kk < 4; kk++) {
                int kb = kk*16;
                unsigned a[2][4], b[4][2];
                #pragma unroll
                for (int mf = 0; mf < 2; mf++)
                    ldm4(a[mf], Gs + (warpM + mf*16 + bTrow)*136 + btoff + kb + bTcol);
                #pragma unroll
                for (int nfp = 0; nfp < 2; nfp++) {
                    unsigned r[4];
                    ldm4t(r, Wp + (kb + bTrow)*72 + obase + nfp*16 + bTcol);
                    b[2*nfp][0] = r[0]; b[2*nfp][1] = r[1];
                    b[2*nfp+1][0] = r[2]; b[2*nfp+1][1] = r[3];
                }
                #pragma unroll
                for (int mf = 0; mf < 2; mf++)
                    #pragma unroll
                    for (int nf = 0; nf < 4; nf++)
                        mma_f16(oacc[mf][nf], a[mf], b[nf]);
            }
            // no trailing sync: next iteration-top barrier orders Gs/W reuse
        }
    }

    // identity piece
    asm volatile("cp.async.wait_group 0;");
    __syncthreads();
    #pragma unroll
    for (int l = 0; l < 4; l++) {
        int idx = tid + l*512;
        int r = idx >> 4, seg = idx & 15;
        *(uint4*)&Gs[r*136 + seg*8] = *(const uint4*)(g_xh + (size_t)(rowBase + r)*NJ + colBase + seg*8);
    }
    __syncthreads();
    {
        const int btoff = warpN & 64;
        const int obase = warpN & 32;
        const __half* Wp = Wb + 4608;
        #pragma unroll
        for (int kk = 0; kk < 4; kk++) {
            int kb = kk*16;
            unsigned a[2][4], b[4][2];
            #pragma unroll
            for (int mf = 0; mf < 2; mf++)
                ldm4(a[mf], Gs + (warpM + mf*16 + bTrow)*136 + btoff + kb + bTcol);
            #pragma unroll
            for (int nfp = 0; nfp < 2; nfp++) {
                unsigned r[4];
                ldm4t(r, Wp + (kb + bTrow)*72 + obase + nfp*16 + bTcol);
                b[2*nfp][0] = r[0]; b[2*nfp][1] = r[1];
                b[2*nfp+1][0] = r[2]; b[2*nfp+1][1] = r[3];
            }
            #pragma unroll
            for (int mf = 0; mf < 2; mf++)
                #pragma unroll
                for (int nf = 0; nf < 4; nf++)
                    mma_f16(oacc[mf][nf], a[mf], b[nf]);
        }
    }
    __syncthreads();

    // epilogue: oacc -> Cs -> relu(+bias+x) -> out
    #pragma unroll
    for (int mf = 0; mf < 2; mf++)
        #pragma unroll
        for (int nf = 0; nf < 4; nf++) {
            int r = warpM + mf*16 + qr, c = warpN + nf*8 + qc*2;
            Cs[r*132 + c]     = oacc[mf][nf][0];
            Cs[r*132 + c + 1] = oacc[mf][nf][1];
            Cs[(r+8)*132 + c]     = oacc[mf][nf][2];
            Cs[(r+8)*132 + c + 1] = oacc[mf][nf][3];
        }
    __syncthreads();
    #pragma unroll
    for (int l = 0; l < 8; l++) {
        int idx = tid + l*512;            // 4096 quads
        int row = idx >> 5, nq = idx & 31;
        int col = colBase + nq*4;
        int o = col & 63, bt = col >> 6;
        int b = bt / 12, t = bt - b*12;
        int w = rowBase + row;
        size_t addr = ((size_t)((b*512 + w)*12 + t))*64 + o;
        float4 c  = *(float4*)&Cs[row*132 + nq*4];
        float4 bi = *(const float4*)(bias + o);
        float4 xr = *(const float4*)(x + addr);
        float4 r;
        r.x = fmaxf(c.x + bi.x + xr.x, 0.f);
        r.y = fmaxf(c.y + bi.y + xr.y, 0.f);
        r.z = fmaxf(c.z + bi.z + xr.z, 0.f);
        r.w = fmaxf(c.w + bi.w + xr.w, 0.f);
        *(float4*)(out + addr) = r;
    }
}

// ---------------- launch ----------------
extern "C" void kernel_launch(void* const* d_in, const int* in_sizes, int n_in,
                              void* d_out, int out_size) {
    (void)in_sizes; (void)n_in; (void)out_size;
    const float* x    = (const float*)d_in[0];
    const float* adj  = (const float*)d_in[1];
    const float* emb  = (const float*)d_in[2];
    const float* W1   = (const float*)d_in[3];
    const float* W2   = (const float*)d_in[4];
    const float* mlpw = (const float*)d_in[5];
    const float* mlpb = (const float*)d_in[6];
    float* out = (float*)d_out;

    const int SMEM = (8*STG + 128*136 + 2*4608) * 2;   // 192512 bytes

    static int configured = 0;
    if (!configured) {
        cudaFuncSetAttribute(k_main, cudaFuncAttributeMaxDynamicSharedMemorySize, SMEM);
        configured = 1;
    }

    k_softmax<<<1, 64>>>(W1, W2);
    k_embed<<<512, 64>>>(emb);
    k_buildA<<<512, 256>>>(adj);
    k_ls<<<512, 256>>>();

    // powers: P2 ; {P3,P4} ; {P5,P6,P7} ; P9
    k_pow<<<dim3(8, 8, 1), 256>>>(0);
    k_pow<<<dim3(8, 8, 2), 256>>>(1);
    k_pow<<<dim3(8, 8, 3), 256>>>(3);
    k_pow<<<dim3(8, 8, 1), 256>>>(6);
    k_combine<<<256, 256>>>();

    k_xh<<<dim3(32, 512), 192>>>(x);
    k_packWh<<<40, 1024>>>(mlpw);

    k_main<<<dim3(NJ/128, NN/128), 512, SMEM>>>(x, mlpb, out);
}

// round 8
// speedup vs baseline: 1.2846x; 1.2846x over previous
#include <cuda_runtime.h>
#include <cuda_fp16.h>
#include <math.h>
#include <stdint.h>

#define NN 512
#define TT 12
#define NJ 24576
#define NNNN (NN*NN)
#define NPC 7            // GEMM1 pieces: P1,P2,P3,T2^2,T2^3,T3^2,T3^3
#define NCHUNK (NPC*8)   // 56

// ---------------- device scratch ----------------
__device__ float g_smW1[40*20];
__device__ float g_smW2[40*20];
__device__ float g_e1[NN*20];
__device__ float g_e2[NN*20];
__device__ float g_A[NN*NN];
__device__ float g_d[NN];
__device__ float g_P[(size_t)9*NNNN];            // powers Ls^1..Ls^9 (slot k-1), slot 7 unused
__device__ __align__(16) __half g_Zh[(size_t)NPC*NNNN]; // pieces fp16, [p][v][w]
__device__ __align__(16) __half g_xh[(size_t)NN*NJ];    // [v][(b*12+t)*64+c]
__device__ __align__(16) __half g_Wh[8*64*64];          // [p][c][o]; p=7 identity weight

// power-product table: P_C = P_A @ P_B (slot indices)
__device__ const int POW_A[7] = {0,0,1,1,2,2,3};
__device__ const int POW_B[7] = {0,1,1,2,2,3,4};
__device__ const int POW_C[7] = {1,2,3,4,5,6,8};

// ---------------- helpers ----------------
__device__ __forceinline__ unsigned f2tf(float f) {
    unsigned u;
    asm("cvt.rna.tf32.f32 %0, %1;" : "=r"(u) : "f"(f));
    return u;
}
__device__ __forceinline__ void mma_tf32(float c[4], const unsigned a[4], const unsigned b[2]) {
    asm volatile("mma.sync.aligned.m16n8k8.row.col.f32.tf32.tf32.f32 "
        "{%0,%1,%2,%3}, {%4,%5,%6,%7}, {%8,%9}, {%0,%1,%2,%3};"
        : "+f"(c[0]), "+f"(c[1]), "+f"(c[2]), "+f"(c[3])
        : "r"(a[0]), "r"(a[1]), "r"(a[2]), "r"(a[3]), "r"(b[0]), "r"(b[1]));
}
__device__ __forceinline__ void mma_f16(float c[4], const unsigned a[4], const unsigned b[2]) {
    asm volatile("mma.sync.aligned.m16n8k16.row.col.f32.f16.f16.f32 "
        "{%0,%1,%2,%3}, {%4,%5,%6,%7}, {%8,%9}, {%0,%1,%2,%3};"
        : "+f"(c[0]), "+f"(c[1]), "+f"(c[2]), "+f"(c[3])
        : "r"(a[0]), "r"(a[1]), "r"(a[2]), "r"(a[3]), "r"(b[0]), "r"(b[1]));
}
__device__ __forceinline__ void ldm4t(unsigned r[4], const __half* p) {
    unsigned a = (unsigned)__cvta_generic_to_shared((void*)p);
    asm volatile("ldmatrix.sync.aligned.m8n8.x4.trans.shared.b16 {%0,%1,%2,%3}, [%4];"
        : "=r"(r[0]), "=r"(r[1]), "=r"(r[2]), "=r"(r[3]) : "r"(a));
}
__device__ __forceinline__ void ldm4(unsigned r[4], const __half* p) {
    unsigned a = (unsigned)__cvta_generic_to_shared((void*)p);
    asm volatile("ldmatrix.sync.aligned.m8n8.x4.shared.b16 {%0,%1,%2,%3}, [%4];"
        : "=r"(r[0]), "=r"(r[1]), "=r"(r[2]), "=r"(r[3]) : "r"(a));
}
__device__ __forceinline__ void cp16(const __half* smem_dst, const __half* gsrc) {
    unsigned sa = (unsigned)__cvta_generic_to_shared((void*)smem_dst);
    asm volatile("cp.async.ca.shared.global [%0], [%1], 16;" :: "r"(sa), "l"(gsrc));
}
__device__ __forceinline__ void cp_commit() { asm volatile("cp.async.commit_group;"); }
__device__ __forceinline__ void cp_wait0() { asm volatile("cp.async.wait_group 0;"); }
__device__ __forceinline__ void cp_wait1() { asm volatile("cp.async.wait_group 1;"); }

// ---------------- preprocessing ----------------
__global__ void k_softmax(const float* __restrict__ W1, const float* __restrict__ W2) {
    int t = threadIdx.x;
    if (t >= 40) return;
    const float* W = (t < 20) ? W1 : W2;
    float* S = (t < 20) ? g_smW1 : g_smW2;
    int c = (t < 20) ? t : t - 20;
    float m = -1e30f;
    for (int r = 0; r < 40; r++) m = fmaxf(m, W[r*20 + c]);
    float e[40];
    float s = 0.f;
    for (int r = 0; r < 40; r++) { e[r] = expf(W[r*20 + c] - m); s += e[r]; }
    float inv = 1.f / s;
    for (int r = 0; r < 40; r++) S[r*20 + c] = e[r] * inv;
}

__global__ void k_embed(const float* __restrict__ emb) {
    int i = blockIdx.x;
    __shared__ float es[40];
    __shared__ float r1[20], r2[20], nrm[2];
    int tid = threadIdx.x;
    if (tid < 40) es[tid] = emb[i*40 + tid];
    __syncthreads();
    if (tid < 20) {
        float s = 0.f;
        for (int q = 0; q < 40; q++) s += es[q] * g_smW1[q*20 + tid];
        r1[tid] = s;
    } else if (tid < 40) {
        int c = tid - 20;
        float s = 0.f;
        for (int q = 0; q < 40; q++) s += es[q] * g_smW2[q*20 + c];
        r2[c] = s;
    }
    __syncthreads();
    if (tid < 2) {
        const float* rr = tid ? r2 : r1;
        float s = 0.f;
        for (int q = 0; q < 20; q++) s += rr[q]*rr[q];
        nrm[tid] = sqrtf(s) + 1e-8f;
    }
    __syncthreads();
    if (tid < 20)      g_e1[i*20 + tid]       = r1[tid]      / nrm[0];
    else if (tid < 40) g_e2[i*20 + (tid-20)]  = r2[tid-20]   / nrm[1];
}

__global__ void k_buildA(const float* __restrict__ adj) {
    int i = blockIdx.x;
    __shared__ float e1s[20];
    __shared__ float red[256];
    int tid = threadIdx.x;
    if (tid < 20) e1s[tid] = g_e1[i*20 + tid];
    __syncthreads();
    float rs = 0.f;
    for (int j = tid; j < NN; j += 256) {
        float dot = 0.f;
        #pragma unroll
        for (int q = 0; q < 20; q++) dot += e1s[q] * g_e2[j*20 + q];
        float ad = adj[i*NN + j];
        float a = (ad > 0.f) ? (dot + ad) : 9e-15f;
        g_A[i*NN + j] = a;
        rs += a;
    }
    red[tid] = rs; __syncthreads();
    for (int s = 128; s > 0; s >>= 1) {
        if (tid < s) red[tid] += red[tid + s];
        __syncthreads();
    }
    if (tid == 0) g_d[i] = 1.f / sqrtf(red[0]);
}

// P1 = Ls
__global__ void k_ls() {
    int i = blockIdx.x;
    float di = g_d[i];
    for (int j = threadIdx.x; j < NN; j += 256)
        g_P[(size_t)i*NN + j] = -(di * g_A[i*NN + j] * g_d[j]);
}

// batched 512^3 tf32 gemm: P_C[z] = P_A[z] @ P_B[z]
__global__ void __launch_bounds__(256) k_pow(int base) {
    int z = base + blockIdx.z;
    const float* A = g_P + (size_t)POW_A[z]*NNNN;
    const float* B = g_P + (size_t)POW_B[z]*NNNN;
    float*       C = g_P + (size_t)POW_C[z]*NNNN;

    __shared__ unsigned As[64*36];
    __shared__ unsigned Bs[32*68];
    const int tid = threadIdx.x;
    const int wid = tid >> 5, lane = tid & 31;
    const int qr = lane >> 2, qc = lane & 3;
    const int warpM = (wid >> 2) * 32;
    const int warpN = (wid & 3) * 16;
    const int row0 = blockIdx.y * 64, col0 = blockIdx.x * 64;
    float acc[2][2][4] = {};
    for (int k0 = 0; k0 < 512; k0 += 32) {
        #pragma unroll
        for (int l = 0; l < 2; l++) {
            int idx = tid + l*256;
            int m = idx >> 3, k4 = (idx & 7) << 2;
            float4 v = *(const float4*)(A + (size_t)(row0 + m)*512 + k0 + k4);
            unsigned* d = &As[m*36 + k4];
            d[0]=f2tf(v.x); d[1]=f2tf(v.y); d[2]=f2tf(v.z); d[3]=f2tf(v.w);
        }
        #pragma unroll
        for (int l = 0; l < 2; l++) {
            int idx = tid + l*256;
            int kr = idx >> 4, n4 = (idx & 15) << 2;
            float4 v = *(const float4*)(B + (size_t)(k0 + kr)*512 + col0 + n4);
            unsigned* d = &Bs[kr*68 + n4];
            d[0]=f2tf(v.x); d[1]=f2tf(v.y); d[2]=f2tf(v.z); d[3]=f2tf(v.w);
        }
        __syncthreads();
        #pragma unroll
        for (int kk = 0; kk < 4; kk++) {
            int kb = kk*8;
            unsigned a[2][4], b[2][2];
            #pragma unroll
            for (int mf = 0; mf < 2; mf++) {
                int m = warpM + mf*16 + qr;
                a[mf][0] = As[m*36 + kb + qc];
                a[mf][1] = As[(m+8)*36 + kb + qc];
                a[mf][2] = As[m*36 + kb + qc + 4];
                a[mf][3] = As[(m+8)*36 + kb + qc + 4];
            }
            #pragma unroll
            for (int nf = 0; nf < 2; nf++) {
                int n = warpN + nf*8 + qr;
                b[nf][0] = Bs[(kb+qc)*68 + n];
                b[nf][1] = Bs[(kb+qc+4)*68 + n];
            }
            #pragma unroll
            for (int mf = 0; mf < 2; mf++)
                #pragma unroll
                for (int nf = 0; nf < 2; nf++)
                    mma_tf32(acc[mf][nf], a[mf], b[nf]);
        }
        __syncthreads();
    }
    #pragma unroll
    for (int mf = 0; mf < 2; mf++)
        #pragma unroll
        for (int nf = 0; nf < 2; nf++)
            #pragma unroll
            for (int e = 0; e < 4; e++) {
                int i = row0 + warpM + mf*16 + qr + (e >> 1)*8;
                int j = col0 + warpN + nf*8 + qc*2 + (e & 1);
                C[(size_t)i*512 + j] = acc[mf][nf][e];
            }
}

// build the 7 fp16 node pieces from powers (elementwise, coalesced)
// Q0=P1, Q1=P2, Q2=P3, Q3=T2^2, Q4=T2^3, Q5=T3^2, Q6=T3^3
__global__ void k_combine() {
    int idx = blockIdx.x*256 + threadIdx.x;   // 65536 float4 groups
    size_t off = (size_t)idx*4;
    int v = (int)(off >> 9), w0 = (int)(off & 511);
    float4 q1 = *(const float4*)(g_P + 0*(size_t)NNNN + off);
    float4 q2 = *(const float4*)(g_P + 1*(size_t)NNNN + off);
    float4 q3 = *(const float4*)(g_P + 2*(size_t)NNNN + off);
    float4 q4 = *(const float4*)(g_P + 3*(size_t)NNNN + off);
    float4 q5 = *(const float4*)(g_P + 4*(size_t)NNNN + off);
    float4 q6 = *(const float4*)(g_P + 5*(size_t)NNNN + off);
    float4 q7 = *(const float4*)(g_P + 6*(size_t)NNNN + off);
    float4 q9 = *(const float4*)(g_P + 8*(size_t)NNNN + off);
    float P1[4] = {q1.x,q1.y,q1.z,q1.w};
    float P2[4] = {q2.x,q2.y,q2.z,q2.w};
    float P3[4] = {q3.x,q3.y,q3.z,q3.w};
    float P4[4] = {q4.x,q4.y,q4.z,q4.w};
    float P5[4] = {q5.x,q5.y,q5.z,q5.w};
    float P6[4] = {q6.x,q6.y,q6.z,q6.w};
    float P7[4] = {q7.x,q7.y,q7.z,q7.w};
    float P9[4] = {q9.x,q9.y,q9.z,q9.w};
    float Z[NPC][4];
    #pragma unroll
    for (int i = 0; i < 4; i++) {
        float D = (w0 + i == v) ? 1.f : 0.f;
        Z[0][i] = P1[i];
        Z[1][i] = P2[i];
        Z[2][i] = P3[i];
        Z[3][i] = 4.f*P4[i] - 4.f*P2[i] + D;                           // T2^2
        Z[4][i] = 8.f*P6[i] - 12.f*P4[i] + 6.f*P2[i] - D;              // T2^3
        Z[5][i] = 16.f*P6[i] - 24.f*P4[i] + 9.f*P2[i];                 // T3^2
        Z[6][i] = 64.f*P9[i] - 144.f*P7[i] + 108.f*P5[i] - 27.f*P3[i]; // T3^3
    }
    #pragma unroll
    for (int p = 0; p < NPC; p++) {
        __half2 h0 = __floats2half2_rn(Z[p][0], Z[p][1]);
        __half2 h1 = __floats2half2_rn(Z[p][2], Z[p][3]);
        uint2 u; u.x = *(unsigned*)&h0; u.y = *(unsigned*)&h1;
        *(uint2*)(g_Zh + (size_t)p*NNNN + off) = u;
    }
}

// g_xh[v][(b*12+t)*64+c] = x[b][v][t][c]
__global__ void k_xh(const float* __restrict__ x) {
    int b = blockIdx.x, v = blockIdx.y;
    int tc = threadIdx.x * 4;
    float4 f = *(const float4*)(x + ((size_t)(b*512 + v)*12)*64 + tc);
    __half2 h0 = __floats2half2_rn(f.x, f.y), h1 = __floats2half2_rn(f.z, f.w);
    uint2 u; u.x = *(unsigned*)&h0; u.y = *(unsigned*)&h1;
    *(uint2*)(g_xh + (size_t)v*NJ + b*768 + tc) = u;
}

// folded weights (B_j = mlp block j, element (o,c) at mlp_w[o*832 + j*64 + c]):
// p0: B4 - 3*B10   (P1)      p1: B5 + 2*B7   (P2)     p2: B6 + 4*B10  (P3)
// p3: B8 (T2^2)  p4: B9 (T2^3)  p5: B11 (T3^2)  p6: B12 (T3^3)
// p7: B0+B1+B2+B3 - B7   (identity)
__global__ void k_packWh(const float* __restrict__ mlp_w) {
    int idx = blockIdx.x*1024 + threadIdx.x;   // 32768 total
    int p = idx >> 12, rem = idx & 4095;
    int c = rem >> 6, o = rem & 63;
    const float* R = mlp_w + o*832 + c;
    float v;
    switch (p) {
        case 0: v = R[4*64] - 3.f*R[10*64]; break;
        case 1: v = R[5*64] + 2.f*R[7*64]; break;
        case 2: v = R[6*64] + 4.f*R[10*64]; break;
        case 3: v = R[8*64]; break;
        case 4: v = R[9*64]; break;
        case 5: v = R[11*64]; break;
        case 6: v = R[12*64]; break;
        default: v = R[0] + R[64] + R[2*64] + R[3*64] - R[7*64]; break;
    }
    g_Wh[idx] = __float2half(v);
}

// ---------------- fused main kernel (512 threads, 16 warps; R6 schedule) ----------------
__global__ void __launch_bounds__(512, 1) k_main(const float* __restrict__ x,
                                                 const float* __restrict__ bias,
                                                 float* __restrict__ out) {
    extern __shared__ __half sm[];
    __half* Ab0 = sm;                    // [64][136] x2
    __half* Bb0 = sm + 2*64*136;         // [64][136] x2
    __half* Gs  = sm + 4*64*136;         // [128][136]
    __half* Whs = Gs + 128*136;          // [8][64][72]
    float*  Cs  = (float*)sm;            // epilogue overlay (128x132 fp32)

    const int tid = threadIdx.x;
    const int wid = tid >> 5, lane = tid & 31;
    const int qr = lane >> 2, qc = lane & 3;
    const int warpM = (wid >> 2) * 32;        // 0,32,64,96
    const int warpN = (wid & 3) * 32;         // 0,32,64,96
    const int rowBase = blockIdx.y * 128;
    const int colBase = blockIdx.x * 128;

    const int g = lane >> 3, lrow = lane & 7;
    const int aTrow = (g >> 1)*8 + lrow, aTcol = (g & 1)*8;
    const int bTrow = (g & 1)*8 + lrow, bTcol = (g >> 1)*8;

    float acc[2][4][4] = {};
    float oacc[2][4][4] = {};

    // prefetch all 8 W pieces
    #pragma unroll
    for (int l = 0; l < 8; l++) {
        int idx = tid + l*512;              // 4096 tasks
        int p = idx >> 9; int rem = idx & 511;
        int c = rem >> 3, seg = rem & 7;
        cp16(&Whs[p*4608 + c*72 + seg*8], g_Wh + (size_t)(p*64 + c)*64 + seg*8);
    }
    // prefetch stage 0 (p=0, kc=0)
    #pragma unroll
    for (int l = 0; l < 2; l++) {
        int idx = tid + l*512;
        int kr = idx >> 4, seg = idx & 15;
        cp16(&Ab0[kr*136 + seg*8], g_Zh + (size_t)kr*512 + rowBase + seg*8);
        cp16(&Bb0[kr*136 + seg*8], g_xh + (size_t)kr*NJ + colBase + seg*8);
    }
    cp_commit();

    int buf = 0;
    for (int s = 0; s < NCHUNK; s++) {
        int kc = s & 7;
        if (s < NCHUNK - 1) {
            int s1 = s + 1;
            int p1 = s1 >> 3, kc1 = s1 & 7;
            __half* Ad = Ab0 + (buf^1)*64*136;
            __half* Bd = Bb0 + (buf^1)*64*136;
            #pragma unroll
            for (int l = 0; l < 2; l++) {
                int idx = tid + l*512;
                int kr = idx >> 4, seg = idx & 15;
                cp16(&Ad[kr*136 + seg*8], g_Zh + (size_t)(p1*512 + kc1*64 + kr)*512 + rowBase + seg*8);
                cp16(&Bd[kr*136 + seg*8], g_xh + (size_t)(kc1*64 + kr)*NJ + colBase + seg*8);
            }
            cp_commit();
            cp_wait1();
        } else {
            cp_wait0();
        }
        __syncthreads();

        const __half* A = Ab0 + buf*64*136;
        const __half* B = Bb0 + buf*64*136;
        #pragma unroll
        for (int kk = 0; kk < 4; kk++) {
            int kb = kk*16;
            unsigned a[2][4], b[4][2];
            #pragma unroll
            for (int mf = 0; mf < 2; mf++)
                ldm4t(a[mf], A + (kb + aTrow)*136 + warpM + mf*16 + aTcol);
            #pragma unroll
            for (int nfp = 0; nfp < 2; nfp++) {
                unsigned r[4];
                ldm4t(r, B + (kb + bTrow)*136 + warpN + nfp*16 + bTcol);
                b[2*nfp][0] = r[0]; b[2*nfp][1] = r[1];
                b[2*nfp+1][0] = r[2]; b[2*nfp+1][1] = r[3];
            }
            #pragma unroll
            for (int mf = 0; mf < 2; mf++)
                #pragma unroll
                for (int nf = 0; nf < 4; nf++)
                    mma_f16(acc[mf][nf], a[mf], b[nf]);
        }
        __syncthreads();

        if (kc == 7) {
            int p = s >> 3;
            // acc -> Gs fp16, reset acc
            #pragma unroll
            for (int mf = 0; mf < 2; mf++)
                #pragma unroll
                for (int nf = 0; nf < 4; nf++) {
                    int r = warpM + mf*16 + qr, c = warpN + nf*8 + qc*2;
                    __half2 h0 = __floats2half2_rn(acc[mf][nf][0], acc[mf][nf][1]);
                    __half2 h1 = __floats2half2_rn(acc[mf][nf][2], acc[mf][nf][3]);
                    *(__half2*)&Gs[r*136 + c] = h0;
                    *(__half2*)&Gs[(r+8)*136 + c] = h1;
                    acc[mf][nf][0]=0.f; acc[mf][nf][1]=0.f; acc[mf][nf][2]=0.f; acc[mf][nf][3]=0.f;
                }
            __syncthreads();
            // GEMM2: oacc += Gs(bt-slice) @ Wh_p
            const int btoff = warpN & 64;
            const int obase = warpN & 32;
            const __half* Wp = Whs + p*4608;
            #pragma unroll
            for (int kk = 0; kk < 4; kk++) {
                int kb = kk*16;
                unsigned a[2][4], b[4][2];
                #pragma unroll
                for (int mf = 0; mf < 2; mf++)
                    ldm4(a[mf], Gs + (warpM + mf*16 + bTrow)*136 + btoff + kb + bTcol);
                #pragma unroll
                for (int nfp = 0; nfp < 2; nfp++) {
                    unsigned r[4];
                    ldm4t(r, Wp + (kb + bTrow)*72 + obase + nfp*16 + bTcol);
                    b[2*nfp][0] = r[0]; b[2*nfp][1] = r[1];
                    b[2*nfp+1][0] = r[2]; b[2*nfp+1][1] = r[3];
                }
                #pragma unroll
                for (int mf = 0; mf < 2; mf++)
                    #pragma unroll
                    for (int nf = 0; nf < 4; nf++)
                        mma_f16(oacc[mf][nf], a[mf], b[nf]);
            }
            __syncthreads();
        }
        buf ^= 1;
    }

    // identity piece: Gs = x tile, then GEMM2 with Wh[7]
    #pragma unroll
    for (int l = 0; l < 4; l++) {
        int idx = tid + l*512;
        int r = idx >> 4, seg = idx & 15;
        *(uint4*)&Gs[r*136 + seg*8] = *(const uint4*)(g_xh + (size_t)(rowBase + r)*NJ + colBase + seg*8);
    }
    __syncthreads();
    {
        const int btoff = warpN & 64;
        const int obase = warpN & 32;
        const __half* Wp = Whs + 7*4608;
        #pragma unroll
        for (int kk = 0; kk < 4; kk++) {
            int kb = kk*16;
            unsigned a[2][4], b[4][2];
            #pragma unroll
            for (int mf = 0; mf < 2; mf++)
                ldm4(a[mf], Gs + (warpM + mf*16 + bTrow)*136 + btoff + kb + bTcol);
            #pragma unroll
            for (int nfp = 0; nfp < 2; nfp++) {
                unsigned r[4];
                ldm4t(r, Wp + (kb + bTrow)*72 + obase + nfp*16 + bTcol);
                b[2*nfp][0] = r[0]; b[2*nfp][1] = r[1];
                b[2*nfp+1][0] = r[2]; b[2*nfp+1][1] = r[3];
            }
            #pragma unroll
            for (int mf = 0; mf < 2; mf++)
                #pragma unroll
                for (int nf = 0; nf < 4; nf++)
                    mma_f16(oacc[mf][nf], a[mf], b[nf]);
        }
    }
    __syncthreads();

    // epilogue: oacc -> Cs -> relu(+bias+x) -> out
    #pragma unroll
    for (int mf = 0; mf < 2; mf++)
        #pragma unroll
        for (int nf = 0; nf < 4; nf++) {
            int r = warpM + mf*16 + qr, c = warpN + nf*8 + qc*2;
            Cs[r*132 + c]     = oacc[mf][nf][0];
            Cs[r*132 + c + 1] = oacc[mf][nf][1];
            Cs[(r+8)*132 + c]     = oacc[mf][nf][2];
            Cs[(r+8)*132 + c + 1] = oacc[mf][nf][3];
        }
    __syncthreads();
    #pragma unroll
    for (int l = 0; l < 8; l++) {
        int idx = tid + l*512;            // 4096 quads
        int row = idx >> 5, nq = idx & 31;
        int col = colBase + nq*4;
        int o = col & 63, bt = col >> 6;
        int b = bt / 12, t = bt - b*12;
        int w = rowBase + row;
        size_t addr = ((size_t)((b*512 + w)*12 + t))*64 + o;
        float4 c  = *(float4*)&Cs[row*132 + nq*4];
        float4 bi = *(const float4*)(bias + o);
        float4 xr = *(const float4*)(x + addr);
        float4 r;
        r.x = fmaxf(c.x + bi.x + xr.x, 0.f);
        r.y = fmaxf(c.y + bi.y + xr.y, 0.f);
        r.z = fmaxf(c.z + bi.z + xr.z, 0.f);
        r.w = fmaxf(c.w + bi.w + xr.w, 0.f);
        *(float4*)(out + addr) = r;
    }
}

// ---------------- launch ----------------
extern "C" void kernel_launch(void* const* d_in, const int* in_sizes, int n_in,
                              void* d_out, int out_size) {
    (void)in_sizes; (void)n_in; (void)out_size;
    const float* x    = (const float*)d_in[0];
    const float* adj  = (const float*)d_in[1];
    const float* emb  = (const float*)d_in[2];
    const float* W1   = (const float*)d_in[3];
    const float* W2   = (const float*)d_in[4];
    const float* mlpw = (const float*)d_in[5];
    const float* mlpb = (const float*)d_in[6];
    float* out = (float*)d_out;

    const int SMEM = (4*64*136 + 128*136 + 8*4608) * 2;   // 178176 bytes

    static int configured = 0;
    if (!configured) {
        cudaFuncSetAttribute(k_main, cudaFuncAttributeMaxDynamicSharedMemorySize, SMEM);
        configured = 1;
    }

    k_softmax<<<1, 64>>>(W1, W2);
    k_embed<<<512, 64>>>(emb);
    k_buildA<<<512, 256>>>(adj);
    k_ls<<<512, 256>>>();

    // powers: P2 ; {P3,P4} ; {P5,P6,P7} ; P9
    k_pow<<<dim3(8, 8, 1), 256>>>(0);
    k_pow<<<dim3(8, 8, 2), 256>>>(1);
    k_pow<<<dim3(8, 8, 3), 256>>>(3);
    k_pow<<<dim3(8, 8, 1), 256>>>(6);
    k_combine<<<256, 256>>>();

    k_xh<<<dim3(32, 512), 192>>>(x);
    k_packWh<<<32, 1024>>>(mlpw);

    k_main<<<dim3(NJ/128, NN/128), 512, SMEM>>>(x, mlpb, out);
}